// round 3
// baseline (speedup 1.0000x reference)
#include <cuda_runtime.h>

#define E_TOTAL  160000
#define N_NODES_ 10000
#define T_EDGES  128
#define NBLK     (E_TOTAL / T_EDGES)   // 1250

// SMEM layout (floats)
#define HS_OFF   0        // Hs[128][128]
#define WB_OFF   16384    // Wbuf[128][128] (also EA/W1 staging during GEMM1)
#define A0_OFF   32768    // Sa0[128][16] = x0*sh0
#define A1_OFF   34816    // Sa1[128][16] = x0
#define A3_OFF   36864    // Sa3[128][16] = (x1 . sh1)/sqrt(3)
#define X1_OFF   38912    // Sx1[128][48]
#define SH_OFF   45056    // Ssh[128][4]
#define DST_OFF  45568    // int[128]
#define SRC_OFF  45696    // int[128]
#define SMEM_FLOATS 45824
#define SMEM_BYTES  (SMEM_FLOATS * 4)   // 183296

__device__ float g_acc[N_NODES_ * 64];
__device__ float g_cnt[N_NODES_];

__global__ void zero_kernel() {
    int i = blockIdx.x * blockDim.x + threadIdx.x;
    if (i < N_NODES_ * 64) g_acc[i] = 0.0f;
    else if (i < N_NODES_ * 64 + N_NODES_) g_cnt[i - N_NODES_ * 64] = 0.0f;
}

__global__ void __launch_bounds__(256, 1) fused_kernel(
    const float* __restrict__ x,    const int* __restrict__ ei,
    const float* __restrict__ ea,   const float* __restrict__ esh,
    const float* __restrict__ w1,   const float* __restrict__ b1,
    const float* __restrict__ w2,   const float* __restrict__ b2)
{
    extern __shared__ float sm[];
    float* Hs  = sm + HS_OFF;
    float* Wb  = sm + WB_OFF;
    float* Sa0 = sm + A0_OFF;
    float* Sa1 = sm + A1_OFF;
    float* Sa3 = sm + A3_OFF;
    float* Sx1 = sm + X1_OFF;
    float* Ssh = sm + SH_OFF;
    int*   Sdst = (int*)(sm + DST_OFF);
    int*   Ssrc = (int*)(sm + SRC_OFF);

    const int t  = threadIdx.x;
    const int v  = t & 15;          // output irrep index this thread owns
    const int g  = t >> 4;          // edge-group 0..15 (edges g, g+16, ..., g+112)
    const int e0 = blockIdx.x * T_EDGES;

    // -------- phase 1: indices + spherical harmonics --------
    if (t < 128) {
        int eg = e0 + t;
        Ssrc[t] = ei[eg];
        Sdst[t] = ei[E_TOTAL + eg];
        float4 s = *(const float4*)(esh + eg * 4);
        Ssh[t * 4 + 0] = s.x; Ssh[t * 4 + 1] = s.y;
        Ssh[t * 4 + 2] = s.z; Ssh[t * 4 + 3] = s.w;
    }
    __syncthreads();

    // -------- phase 2: gather x[src], precompute a-vectors --------
    {
        int e    = t & 127;
        int part = t >> 7;
        int src  = Ssrc[e];
        const float4* xr = (const float4*)(x + src * 64);
        if (part == 0) {
            float sh0 = Ssh[e * 4 + 0];
            #pragma unroll
            for (int q = 0; q < 4; q++) {
                float4 xv = xr[q];
                int u = q * 4;
                Sa1[e*16 + u + 0] = xv.x;  Sa0[e*16 + u + 0] = xv.x * sh0;
                Sa1[e*16 + u + 1] = xv.y;  Sa0[e*16 + u + 1] = xv.y * sh0;
                Sa1[e*16 + u + 2] = xv.z;  Sa0[e*16 + u + 2] = xv.z * sh0;
                Sa1[e*16 + u + 3] = xv.w;  Sa0[e*16 + u + 3] = xv.w * sh0;
            }
        } else {
            float s1x = Ssh[e*4 + 1], s1y = Ssh[e*4 + 2], s1z = Ssh[e*4 + 3];
            float x1l[48];
            #pragma unroll
            for (int q = 0; q < 12; q++) {
                float4 xv = xr[4 + q];
                x1l[q*4 + 0] = xv.x; x1l[q*4 + 1] = xv.y;
                x1l[q*4 + 2] = xv.z; x1l[q*4 + 3] = xv.w;
                *(float4*)(Sx1 + e*48 + q*4) = xv;
            }
            #pragma unroll
            for (int u = 0; u < 16; u++) {
                float d = x1l[u*3+0]*s1x + x1l[u*3+1]*s1y + x1l[u*3+2]*s1z;
                Sa3[e*16 + u] = d * 0.57735026918962576f;  // 1/sqrt(3)
            }
        }
    }

    // -------- GEMM1: H = relu(EA @ W1 + b1), result -> Hs --------
    float acc[8][8];
    #pragma unroll
    for (int j = 0; j < 8; j++)
        #pragma unroll
        for (int u = 0; u < 8; u++) acc[j][u] = 0.0f;

    #pragma unroll 1
    for (int fi = 0; fi < 2; fi++) {
        __syncthreads();
        // stage EA chunk [128 edges][64 feats] into Wb[0..8192)
        #pragma unroll
        for (int i = 0; i < 8; i++) {
            int lin = t + i * 256;          // [0, 2048)
            int e  = lin >> 4, f4 = lin & 15;
            *(float4*)(Wb + e*64 + f4*4) =
                *(const float4*)(ea + (e0 + e)*128 + fi*64 + f4*4);
        }
        // stage W1 chunk [64 f][128 c] into Wb[8192..16384)
        #pragma unroll
        for (int i = 0; i < 8; i++) {
            int lin = t + i * 256;          // [0, 2048)
            int ff = lin >> 5, c4 = lin & 31;
            *(float4*)(Wb + 8192 + ff*128 + c4*4) =
                *(const float4*)(w1 + (fi*64 + ff)*128 + c4*4);
        }
        __syncthreads();
        const float* EAs = Wb;
        const float* W1s = Wb + 8192;
        #pragma unroll 1
        for (int f = 0; f < 64; f += 4) {
            float av[8][4];
            #pragma unroll
            for (int j = 0; j < 8; j++) {
                float4 tv = *(const float4*)(EAs + (g + 16*j)*64 + f);
                av[j][0]=tv.x; av[j][1]=tv.y; av[j][2]=tv.z; av[j][3]=tv.w;
            }
            #pragma unroll
            for (int cc = 0; cc < 4; cc++) {
                float wf[8];
                #pragma unroll
                for (int u = 0; u < 8; u++) wf[u] = W1s[(f+cc)*128 + v + 16*u];
                #pragma unroll
                for (int j = 0; j < 8; j++)
                    #pragma unroll
                    for (int u = 0; u < 8; u++)
                        acc[j][u] = fmaf(av[j][cc], wf[u], acc[j][u]);
            }
        }
    }
    // bias + relu -> Hs
    #pragma unroll
    for (int u = 0; u < 8; u++) {
        float bb = b1[v + 16*u];
        #pragma unroll
        for (int j = 0; j < 8; j++)
            Hs[(g + 16*j)*128 + v + 16*u] = fmaxf(acc[j][u] + bb, 0.0f);
    }

    // -------- GEMM2 chunks fused with tensor product --------
    float s0[8], t1[8], o1[8][3];
    #pragma unroll
    for (int j = 0; j < 8; j++) {
        s0[j] = 0.0f; t1[j] = 0.0f;
        o1[j][0] = 0.0f; o1[j][1] = 0.0f; o1[j][2] = 0.0f;
    }

    #pragma unroll 1
    for (int ch = 0; ch < 8; ch++) {
        __syncthreads();   // prior Wb reads (GEMM1 / prev chunk) complete
        // stage W2 chunk [128 c][128 k] into Wb
        #pragma unroll
        for (int i = 0; i < 16; i++) {
            int lin = t + i * 256;          // [0, 4096)
            int c = lin >> 5, k4 = lin & 31;
            *(float4*)(Wb + c*128 + k4*4) =
                *(const float4*)(w2 + c*1024 + ch*128 + k4*4);
        }
        __syncthreads();

        #pragma unroll
        for (int j = 0; j < 8; j++)
            #pragma unroll
            for (int u = 0; u < 8; u++) acc[j][u] = 0.0f;

        #pragma unroll 1
        for (int c = 0; c < 128; c += 4) {
            float hv[8][4];
            #pragma unroll
            for (int j = 0; j < 8; j++) {
                float4 tv = *(const float4*)(Hs + (g + 16*j)*128 + c);
                hv[j][0]=tv.x; hv[j][1]=tv.y; hv[j][2]=tv.z; hv[j][3]=tv.w;
            }
            #pragma unroll
            for (int cc = 0; cc < 4; cc++) {
                float wf[8];
                #pragma unroll
                for (int u = 0; u < 8; u++) wf[u] = Wb[(c+cc)*128 + v + 16*u];
                #pragma unroll
                for (int j = 0; j < 8; j++)
                    #pragma unroll
                    for (int u = 0; u < 8; u++)
                        acc[j][u] = fmaf(hv[j][cc], wf[u], acc[j][u]);
            }
        }

        // consume this w-chunk into TP register accumulators.
        // k = ch*128 + u*16 + v ; p = ch/2 ; u in [ub, ub+8)
        const int p  = ch >> 1;
        const int ub = (ch & 1) * 8;
        float bf[8];
        #pragma unroll
        for (int u = 0; u < 8; u++) bf[u] = b2[ch*128 + v + 16*u];

        if (p == 0) {
            #pragma unroll
            for (int j = 0; j < 8; j++) {
                const float* A = Sa0 + (g + 16*j)*16 + ub;
                #pragma unroll
                for (int u = 0; u < 8; u++)
                    s0[j] = fmaf(A[u], acc[j][u] + bf[u], s0[j]);
            }
        } else if (p == 1) {
            #pragma unroll
            for (int j = 0; j < 8; j++) {
                const float* A = Sa1 + (g + 16*j)*16 + ub;
                #pragma unroll
                for (int u = 0; u < 8; u++)
                    t1[j] = fmaf(A[u], acc[j][u] + bf[u], t1[j]);
            }
        } else if (p == 2) {
            #pragma unroll
            for (int j = 0; j < 8; j++) {
                const float* X = Sx1 + (g + 16*j)*48 + ub*3;
                #pragma unroll
                for (int u = 0; u < 8; u++) {
                    float wv = acc[j][u] + bf[u];
                    o1[j][0] = fmaf(X[u*3+0], wv, o1[j][0]);
                    o1[j][1] = fmaf(X[u*3+1], wv, o1[j][1]);
                    o1[j][2] = fmaf(X[u*3+2], wv, o1[j][2]);
                }
            }
        } else {
            #pragma unroll
            for (int j = 0; j < 8; j++) {
                const float* A = Sa3 + (g + 16*j)*16 + ub;
                #pragma unroll
                for (int u = 0; u < 8; u++)
                    s0[j] = fmaf(A[u], acc[j][u] + bf[u], s0[j]);
            }
        }
    }

    // -------- epilogue: scale + scatter-add --------
    const float alpha = 0.17677669529663689f;  // 1/sqrt(2*MUL)
    #pragma unroll
    for (int j = 0; j < 8; j++) {
        int e   = g + 16*j;
        int dst = Sdst[e];
        float sh0 = Ssh[e*4 + 0];
        float s1x = Ssh[e*4 + 1], s1y = Ssh[e*4 + 2], s1z = Ssh[e*4 + 3];
        float* base = g_acc + dst * 64;
        atomicAdd(base + v, alpha * s0[j]);
        atomicAdd(base + 16 + v*3 + 0, alpha * (t1[j]*s1x + sh0*o1[j][0]));
        atomicAdd(base + 16 + v*3 + 1, alpha * (t1[j]*s1y + sh0*o1[j][1]));
        atomicAdd(base + 16 + v*3 + 2, alpha * (t1[j]*s1z + sh0*o1[j][2]));
        if (v == 0) atomicAdd(&g_cnt[dst], 1.0f);
    }
}

__global__ void finalize_kernel(const float* __restrict__ x, float* __restrict__ out) {
    int i = blockIdx.x * blockDim.x + threadIdx.x;
    if (i < N_NODES_ * 64) {
        int node = i >> 6;
        out[i] = g_acc[i] / fmaxf(g_cnt[node], 1.0f) + x[i];
    }
}

extern "C" void kernel_launch(void* const* d_in, const int* in_sizes, int n_in,
                              void* d_out, int out_size)
{
    const float* x   = (const float*)d_in[0];
    const int*   ei  = (const int*)  d_in[1];
    const float* ea  = (const float*)d_in[2];
    const float* esh = (const float*)d_in[3];
    const float* w1  = (const float*)d_in[4];
    const float* b1  = (const float*)d_in[5];
    const float* w2  = (const float*)d_in[6];
    const float* b2  = (const float*)d_in[7];
    float* out = (float*)d_out;

    cudaFuncSetAttribute(fused_kernel,
                         cudaFuncAttributeMaxDynamicSharedMemorySize, SMEM_BYTES);

    int ztot = N_NODES_ * 64 + N_NODES_;
    zero_kernel<<<(ztot + 255) / 256, 256>>>();
    fused_kernel<<<NBLK, 256, SMEM_BYTES>>>(x, ei, ea, esh, w1, b1, w2, b2);
    finalize_kernel<<<(N_NODES_ * 64 + 255) / 256, 256>>>(x, out);
}

// round 5
// speedup vs baseline: 2.3276x; 2.3276x over previous
#include <cuda_runtime.h>
#include <cuda_bf16.h>
#include <cstdint>

#define E_TOTAL 160000
#define NNODES  10000
#define NBLK    1250

#define SP   136                 // padded row stride (bf16 elems)
#define SPB  272                 // row stride bytes
#define BUF  (128 * SPB)         // 34816 bytes: one 128x136 bf16 buffer

// ---------------- SMEM layout (bytes) ----------------
#define AB_OFF 0                 // A operand: hi @ +0, lo @ +BUF   (EA tile, later H tile)
#define WB_OFF (2 * BUF)         // B operand: hi @ +0, lo @ +BUF   (W1T, later W2T chunks)
#define FL_OFF (4 * BUF)         // 139264: float region
// float-indexed offsets within FL region
#define SA0  0                   // x0*sh0      [128][16]
#define SA1  2048                // x0          [128][16]
#define SA3  4096                // dot/sqrt3   [128][16]
#define SX1  6144                // x1          [128][48]
#define SSH  12288               // sh          [128][4]
#define SDST 12800               // int [128]
#define SSRC 12928               // int [128]
#define SB1  13056               // b1 [128]
#define SB2  13184               // b2 [1024]
#define NFL  14208
#define SMEM_BYTES (FL_OFF + NFL * 4)   // 196096

__device__ float g_acc[NNODES * 64];
__device__ float g_cnt[NNODES];
__device__ __align__(16) unsigned char g_w1s[2 * BUF];       // W1T hi + lo, padded layout
__device__ __align__(16) unsigned char g_w2s[8][2 * BUF];    // per N-chunk W2T hi + lo

// ---------------- helpers ----------------
__device__ __forceinline__ uint32_t smem_u32(const void* p) {
    uint32_t a;
    asm("{ .reg .u64 t; cvta.to.shared.u64 t, %1; cvt.u32.u64 %0, t; }" : "=r"(a) : "l"(p));
    return a;
}
__device__ __forceinline__ void ldsm_x4(uint32_t* r, uint32_t addr) {
    asm volatile("ldmatrix.sync.aligned.m8n8.x4.shared.b16 {%0,%1,%2,%3}, [%4];"
        : "=r"(r[0]), "=r"(r[1]), "=r"(r[2]), "=r"(r[3]) : "r"(addr));
}
__device__ __forceinline__ void mma16816(float* c, const uint32_t* a, const uint32_t* b) {
    asm volatile("mma.sync.aligned.m16n8k16.row.col.f32.bf16.bf16.f32 "
        "{%0,%1,%2,%3}, {%4,%5,%6,%7}, {%8,%9}, {%0,%1,%2,%3};"
        : "+f"(c[0]), "+f"(c[1]), "+f"(c[2]), "+f"(c[3])
        : "r"(a[0]), "r"(a[1]), "r"(a[2]), "r"(a[3]), "r"(b[0]), "r"(b[1]));
}
__device__ __forceinline__ uint32_t pk(float a, float b) {
    uint32_t ua = __bfloat16_as_ushort(__float2bfloat16_rn(a));
    uint32_t ub = __bfloat16_as_ushort(__float2bfloat16_rn(b));
    return ua | (ub << 16);
}
__device__ __forceinline__ float blo(float a) {
    return a - __bfloat162float(__float2bfloat16_rn(a));
}

// One 128x128x128 GEMM with 3-pass bf16 error compensation.
// acc += Ah*Bh + Ah*Bl + Al*Bh.  A row-major [m][k], B stored n-major [n][k].
__device__ __forceinline__ void gemm3(float acc[16][4],
                                      uint32_t a_hi, uint32_t a_lo,
                                      uint32_t w_hi, uint32_t w_lo,
                                      uint32_t aoff, uint32_t boff) {
    #pragma unroll
    for (int kp = 0; kp < 4; kp++) {        // k-pair = 32 cols
        uint32_t Ah[2][4], Al[2][4];
        ldsm_x4(Ah[0], a_hi + aoff + kp * 64);
        ldsm_x4(Ah[1], a_hi + aoff + kp * 64 + 32);
        ldsm_x4(Al[0], a_lo + aoff + kp * 64);
        ldsm_x4(Al[1], a_lo + aoff + kp * 64 + 32);
        #pragma unroll
        for (int nt = 0; nt < 16; nt++) {
            uint32_t Bh[4], Bl[4];
            uint32_t wb = (uint32_t)nt * (8 * SPB) + boff + kp * 64;
            ldsm_x4(Bh, w_hi + wb);
            ldsm_x4(Bl, w_lo + wb);
            mma16816(acc[nt], Ah[0], Bh);     mma16816(acc[nt], Ah[1], Bh + 2);
            mma16816(acc[nt], Ah[0], Bl);     mma16816(acc[nt], Ah[1], Bl + 2);
            mma16816(acc[nt], Al[0], Bh);     mma16816(acc[nt], Al[1], Bh + 2);
        }
    }
}

// ---------------- small kernels ----------------
__global__ void zero_kernel() {
    int i = blockIdx.x * blockDim.x + threadIdx.x;
    if (i < NNODES * 64) g_acc[i] = 0.0f;
    else if (i < NNODES * 64 + NNODES) g_cnt[i - NNODES * 64] = 0.0f;
}

// W1T[h][f] = w1[f][h] as bf16 hi/lo, padded rows
__global__ void prep_w1(const float* __restrict__ w1) {
    int t = blockIdx.x * 256 + threadIdx.x;
    if (t >= 128 * 64) return;
    int h = t >> 6, f = (t & 63) * 2;
    float v0 = w1[f * 128 + h], v1 = w1[(f + 1) * 128 + h];
    uint32_t off = (uint32_t)h * SPB + (uint32_t)f * 2;
    *(uint32_t*)(g_w1s + off)       = pk(v0, v1);
    *(uint32_t*)(g_w1s + BUF + off) = pk(blo(v0), blo(v1));
}

// W2T chunk c: row n (local out col), col f (hidden): w2[f][c*128+n]
__global__ void prep_w2(const float* __restrict__ w2) {
    int t = blockIdx.x * 256 + threadIdx.x;
    if (t >= 8 * 128 * 64) return;
    int c = t >> 13, n = (t >> 6) & 127, f = (t & 63) * 2;
    int kg = c * 128 + n;
    float v0 = w2[f * 1024 + kg], v1 = w2[(f + 1) * 1024 + kg];
    uint32_t off = (uint32_t)n * SPB + (uint32_t)f * 2;
    *(uint32_t*)(g_w2s[c] + off)       = pk(v0, v1);
    *(uint32_t*)(g_w2s[c] + BUF + off) = pk(blo(v0), blo(v1));
}

// ---------------- main fused kernel ----------------
__global__ void __launch_bounds__(256, 1) fused_kernel(
    const float* __restrict__ x,  const int* __restrict__ ei,
    const float* __restrict__ ea, const float* __restrict__ esh,
    const float* __restrict__ b1, const float* __restrict__ b2)
{
    extern __shared__ unsigned char sm[];
    unsigned char* ABc = sm + AB_OFF;
    float* F   = (float*)(sm + FL_OFF);
    float* Sa0 = F + SA0;
    float* Sa1 = F + SA1;
    float* Sa3 = F + SA3;
    float* Sx1 = F + SX1;
    float* Ssh = F + SSH;
    int* Sdst  = (int*)(F + SDST);
    int* Ssrc  = (int*)(F + SSRC);
    float* b1s = F + SB1;
    float* b2s = F + SB2;

    const int tid = threadIdx.x;
    const int wid = tid >> 5, lid = tid & 31;
    const int e0  = blockIdx.x * 128;
    const uint32_t sb = smem_u32(sm);

    // per-thread fragment geometry
    const int m0 = wid * 16;
    const int r0 = m0 + (lid >> 2), r1 = r0 + 8;   // the two edge-rows this thread owns
    const int cb = (lid & 3) * 2;                  // base output col within 8-tile
    const uint32_t aoff = (uint32_t)(m0 + (lid & 15)) * SPB + (uint32_t)((lid >> 4) * 8) * 2;
    const uint32_t boff = (uint32_t)(lid & 7) * SPB + (uint32_t)(lid >> 3) * 16;

    // ---- stage biases ----
    if (tid < 128) b1s[tid] = b1[tid];
    #pragma unroll
    for (int i = 0; i < 4; i++) b2s[tid + i * 256] = b2[tid + i * 256];

    // ---- phase 1: indices + sh ----
    if (tid < 128) {
        int eg = e0 + tid;
        Ssrc[tid] = ei[eg];
        Sdst[tid] = ei[E_TOTAL + eg];
        float4 s = *(const float4*)(esh + (size_t)eg * 4);
        Ssh[tid*4+0] = s.x; Ssh[tid*4+1] = s.y; Ssh[tid*4+2] = s.z; Ssh[tid*4+3] = s.w;
    }
    __syncthreads();

    // ---- phase 2: gather x[src] + TP precompute ----
    {
        int e = tid & 127, part = tid >> 7;
        int src = Ssrc[e];
        const float4* xr = (const float4*)(x + (size_t)src * 64);
        if (part == 0) {
            float sh0 = Ssh[e*4];
            #pragma unroll
            for (int q = 0; q < 4; q++) {
                float4 xv = xr[q];
                int u = q * 4;
                Sa1[e*16+u+0] = xv.x;  Sa0[e*16+u+0] = xv.x * sh0;
                Sa1[e*16+u+1] = xv.y;  Sa0[e*16+u+1] = xv.y * sh0;
                Sa1[e*16+u+2] = xv.z;  Sa0[e*16+u+2] = xv.z * sh0;
                Sa1[e*16+u+3] = xv.w;  Sa0[e*16+u+3] = xv.w * sh0;
            }
        } else {
            float s1x = Ssh[e*4+1], s1y = Ssh[e*4+2], s1z = Ssh[e*4+3];
            float x1l[48];
            #pragma unroll
            for (int q = 0; q < 12; q++) {
                float4 xv = xr[4 + q];
                x1l[q*4+0]=xv.x; x1l[q*4+1]=xv.y; x1l[q*4+2]=xv.z; x1l[q*4+3]=xv.w;
                *(float4*)(Sx1 + e*48 + q*4) = xv;
            }
            #pragma unroll
            for (int u = 0; u < 16; u++) {
                float d = x1l[u*3]*s1x + x1l[u*3+1]*s1y + x1l[u*3+2]*s1z;
                Sa3[e*16+u] = d * 0.57735026918962576f;
            }
        }
    }

    // ---- EA tile -> bf16 hi/lo into A buffer ----
    {
        int r = tid >> 1, half = tid & 1;
        const float4* rowp = (const float4*)(ea + (size_t)(e0 + r) * 128 + half * 64);
        #pragma unroll
        for (int j = 0; j < 16; j++) {
            float4 v = rowp[j];
            int k = half * 64 + j * 4;
            uint32_t* hi = (uint32_t*)(ABc + (uint32_t)r * SPB + (uint32_t)k * 2);
            uint32_t* lo = (uint32_t*)(ABc + BUF + (uint32_t)r * SPB + (uint32_t)k * 2);
            hi[0] = pk(v.x, v.y);           hi[1] = pk(v.z, v.w);
            lo[0] = pk(blo(v.x), blo(v.y)); lo[1] = pk(blo(v.z), blo(v.w));
        }
    }
    // ---- stage W1 (flat 68KB copy) ----
    {
        const float4* src = (const float4*)g_w1s;
        float4* dst = (float4*)(sm + WB_OFF);
        #pragma unroll
        for (int i = 0; i < 17; i++) dst[tid + i * 256] = src[tid + i * 256];
    }
    __syncthreads();

    // ---- GEMM1: H = relu(EA @ W1 + b1) ----
    float acc[16][4];
    #pragma unroll
    for (int nt = 0; nt < 16; nt++)
        #pragma unroll
        for (int q = 0; q < 4; q++) acc[nt][q] = 0.0f;

    gemm3(acc, sb + AB_OFF, sb + AB_OFF + BUF, sb + WB_OFF, sb + WB_OFF + BUF, aoff, boff);
    __syncthreads();   // all warps done reading EA from A buffer

    // writeback H (bias+relu) as bf16 hi/lo into A buffer
    #pragma unroll
    for (int nt = 0; nt < 16; nt++) {
        int c = cb + 8 * nt;
        float h0 = fmaxf(acc[nt][0] + b1s[c],     0.0f);
        float h1 = fmaxf(acc[nt][1] + b1s[c + 1], 0.0f);
        float h2 = fmaxf(acc[nt][2] + b1s[c],     0.0f);
        float h3 = fmaxf(acc[nt][3] + b1s[c + 1], 0.0f);
        *(uint32_t*)(ABc + (uint32_t)r0 * SPB + (uint32_t)c * 2)       = pk(h0, h1);
        *(uint32_t*)(ABc + BUF + (uint32_t)r0 * SPB + (uint32_t)c * 2) = pk(blo(h0), blo(h1));
        *(uint32_t*)(ABc + (uint32_t)r1 * SPB + (uint32_t)c * 2)       = pk(h2, h3);
        *(uint32_t*)(ABc + BUF + (uint32_t)r1 * SPB + (uint32_t)c * 2) = pk(blo(h2), blo(h3));
    }

    // ---- GEMM2 chunks + TP consumption ----
    float s0[2][4], t1[2][4], o1[2][4][3];
    #pragma unroll
    for (int rr = 0; rr < 2; rr++)
        #pragma unroll
        for (int vi = 0; vi < 4; vi++) {
            s0[rr][vi] = 0.0f; t1[rr][vi] = 0.0f;
            o1[rr][vi][0] = 0.0f; o1[rr][vi][1] = 0.0f; o1[rr][vi][2] = 0.0f;
        }

    #pragma unroll 1
    for (int ch = 0; ch < 8; ch++) {
        __syncthreads();   // prior W-buffer reads complete (and H writes on first iter)
        {
            const float4* src = (const float4*)(g_w2s[ch]);
            float4* dst = (float4*)(sm + WB_OFF);
            #pragma unroll
            for (int i = 0; i < 17; i++) dst[tid + i * 256] = src[tid + i * 256];
        }
        __syncthreads();

        #pragma unroll
        for (int nt = 0; nt < 16; nt++)
            #pragma unroll
            for (int q = 0; q < 4; q++) acc[nt][q] = 0.0f;

        gemm3(acc, sb + AB_OFF, sb + AB_OFF + BUF, sb + WB_OFF, sb + WB_OFF + BUF, aoff, boff);

        // epilogue: consume chunk into TP register accumulators.
        // global col k = ch*128 + c_local ; path p = ch>>1 ; u = (ch&1)*8 + c_local/16 ; v = c_local%16
        const int p  = ch >> 1;
        const int ub = (ch & 1) * 8;
        const float* b2c = b2s + ch * 128;

        if (p == 2) {
            #pragma unroll
            for (int nt = 0; nt < 16; nt++) {
                int u = ub + (nt >> 1);
                float xa0 = Sx1[r0*48 + u*3 + 0], xb0 = Sx1[r0*48 + u*3 + 1], xc0 = Sx1[r0*48 + u*3 + 2];
                float xa1 = Sx1[r1*48 + u*3 + 0], xb1 = Sx1[r1*48 + u*3 + 1], xc1 = Sx1[r1*48 + u*3 + 2];
                #pragma unroll
                for (int d = 0; d < 2; d++) {
                    float bb = b2c[cb + 8*nt + d];
                    int vi = (nt & 1) * 2 + d;
                    float w0 = acc[nt][d]     + bb;
                    float w1 = acc[nt][2 + d] + bb;
                    o1[0][vi][0] = fmaf(xa0, w0, o1[0][vi][0]);
                    o1[0][vi][1] = fmaf(xb0, w0, o1[0][vi][1]);
                    o1[0][vi][2] = fmaf(xc0, w0, o1[0][vi][2]);
                    o1[1][vi][0] = fmaf(xa1, w1, o1[1][vi][0]);
                    o1[1][vi][1] = fmaf(xb1, w1, o1[1][vi][1]);
                    o1[1][vi][2] = fmaf(xc1, w1, o1[1][vi][2]);
                }
            }
        } else {
            const float* A = (p == 0) ? Sa0 : (p == 1) ? Sa1 : Sa3;
            float a0[8], a1[8];
            #pragma unroll
            for (int u = 0; u < 8; u++) {
                a0[u] = A[r0*16 + ub + u];
                a1[u] = A[r1*16 + ub + u];
            }
            if (p == 1) {
                #pragma unroll
                for (int nt = 0; nt < 16; nt++) {
                    int u = nt >> 1;
                    #pragma unroll
                    for (int d = 0; d < 2; d++) {
                        float bb = b2c[cb + 8*nt + d];
                        int vi = (nt & 1) * 2 + d;
                        t1[0][vi] = fmaf(a0[u], acc[nt][d]     + bb, t1[0][vi]);
                        t1[1][vi] = fmaf(a1[u], acc[nt][2 + d] + bb, t1[1][vi]);
                    }
                }
            } else {
                #pragma unroll
                for (int nt = 0; nt < 16; nt++) {
                    int u = nt >> 1;
                    #pragma unroll
                    for (int d = 0; d < 2; d++) {
                        float bb = b2c[cb + 8*nt + d];
                        int vi = (nt & 1) * 2 + d;
                        s0[0][vi] = fmaf(a0[u], acc[nt][d]     + bb, s0[0][vi]);
                        s0[1][vi] = fmaf(a1[u], acc[nt][2 + d] + bb, s0[1][vi]);
                    }
                }
            }
        }
    }

    // ---- scatter-add ----
    {
        const float alpha = 0.17677669529663689f;  // 1/sqrt(2*16)
        #pragma unroll
        for (int rr = 0; rr < 2; rr++) {
            int e = rr ? r1 : r0;
            int dst = Sdst[e];
            float sh0 = Ssh[e*4+0];
            float s1x = Ssh[e*4+1], s1y = Ssh[e*4+2], s1z = Ssh[e*4+3];
            float* base = g_acc + (size_t)dst * 64;
            #pragma unroll
            for (int vi = 0; vi < 4; vi++) {
                int v = cb + (vi >> 1) * 8 + (vi & 1);
                atomicAdd(base + v, alpha * s0[rr][vi]);
                atomicAdd(base + 16 + v*3 + 0, alpha * (t1[rr][vi]*s1x + sh0*o1[rr][vi][0]));
                atomicAdd(base + 16 + v*3 + 1, alpha * (t1[rr][vi]*s1y + sh0*o1[rr][vi][1]));
                atomicAdd(base + 16 + v*3 + 2, alpha * (t1[rr][vi]*s1z + sh0*o1[rr][vi][2]));
            }
            if ((lid & 3) == 0) atomicAdd(&g_cnt[dst], 1.0f);
        }
    }
}

__global__ void finalize_kernel(const float* __restrict__ x, float* __restrict__ out) {
    int i = blockIdx.x * blockDim.x + threadIdx.x;
    if (i < NNODES * 64) {
        int node = i >> 6;
        out[i] = g_acc[i] / fmaxf(g_cnt[node], 1.0f) + x[i];
    }
}

extern "C" void kernel_launch(void* const* d_in, const int* in_sizes, int n_in,
                              void* d_out, int out_size)
{
    const float* x   = (const float*)d_in[0];
    const int*   ei  = (const int*)  d_in[1];
    const float* ea  = (const float*)d_in[2];
    const float* esh = (const float*)d_in[3];
    const float* w1  = (const float*)d_in[4];
    const float* b1  = (const float*)d_in[5];
    const float* w2  = (const float*)d_in[6];
    const float* b2  = (const float*)d_in[7];
    float* out = (float*)d_out;

    cudaFuncSetAttribute(fused_kernel,
                         cudaFuncAttributeMaxDynamicSharedMemorySize, SMEM_BYTES);

    int ztot = NNODES * 64 + NNODES;
    zero_kernel<<<(ztot + 255) / 256, 256>>>();
    prep_w1<<<(128 * 64 + 255) / 256, 256>>>(w1);
    prep_w2<<<(8 * 128 * 64 + 255) / 256, 256>>>(w2);
    fused_kernel<<<NBLK, 256, SMEM_BYTES>>>(x, ei, ea, esh, b1, b2);
    finalize_kernel<<<(NNODES * 64 + 255) / 256, 256>>>(x, out);
}